// round 9
// baseline (speedup 1.0000x reference)
#include <cuda_runtime.h>

#define N_NODES 50000
#define N_EDGES 600000
#define D 128
#define CAP 64            // per-node neighbor bucket capacity (Poisson λ=12)
#define BN_EPS 1e-5f

typedef unsigned long long ull;

// Scratch (allocation-free rule: __device__ globals)
__device__ __align__(16) float g_h [N_NODES * D];   // x + aggregated neighbors
__device__ __align__(16) float g_h1[N_NODES * D];   // relu(h @ W1 + b1)
__device__ int   g_cnt [N_NODES];                   // in-degree counters
__device__ int   g_srcs[N_NODES * CAP];             // bucketed src lists
__device__ float g_sum[D];
__device__ float g_sq [D];
__device__ __align__(16) float g_W2l [D * 2];       // W2 @ Wl
__device__ __align__(16) float g_Weff[D * 2];
__device__ float g_ceff[2];

#define FMA2(d, a, b) \
    asm("fma.rn.f32x2 %0, %1, %2, %3;" : "=l"(d) : "l"(a), "l"(b), "l"(d))
#define UNPK(lo, hi, v) do { unsigned _u0, _u1; \
    asm("mov.b64 {%0, %1}, %2;" : "=r"(_u0), "=r"(_u1) : "l"(v)); \
    lo = __uint_as_float(_u0); hi = __uint_as_float(_u1); } while (0)

// ---------------------------------------------------------------------------
// Kernel 1 (k_pre): zero counters + stat accumulators + W2l = W2 @ Wl.
// ---------------------------------------------------------------------------
#define NB_CNT ((N_NODES + 255) / 256)
__global__ void k_pre(const float* __restrict__ W2, const float* __restrict__ Wl) {
    int b = blockIdx.x;
    if (b < NB_CNT) {
        int i = b * 256 + threadIdx.x;
        if (i < N_NODES) g_cnt[i] = 0;
        return;
    }
    if (b < NB_CNT + 16) {
        int f    = (b - NB_CNT) * 8 + (threadIdx.x >> 5);
        int lane = threadIdx.x & 31;
        float4 a  = __ldg((const float4*)(W2 + f * D) + lane);
        float4 w0 = __ldg((const float4*)Wl + lane * 2 + 0);
        float4 w1 = __ldg((const float4*)Wl + lane * 2 + 1);
        float s0 = a.x * w0.x + a.y * w0.z + a.z * w1.x + a.w * w1.z;
        float s1 = a.x * w0.y + a.y * w0.w + a.z * w1.y + a.w * w1.w;
        #pragma unroll
        for (int o = 16; o > 0; o >>= 1) {
            s0 += __shfl_down_sync(0xFFFFFFFFu, s0, o);
            s1 += __shfl_down_sync(0xFFFFFFFFu, s1, o);
        }
        if (lane == 0) {
            g_W2l[f * 2 + 0] = s0;
            g_W2l[f * 2 + 1] = s1;
        }
        return;
    }
    if (threadIdx.x < D) {
        g_sum[threadIdx.x] = 0.f;
        g_sq [threadIdx.x] = 0.f;
    }
}

// ---------------------------------------------------------------------------
// Kernel 2 (k_place): bucket edges by dst. One thread per edge (int32 index).
// ---------------------------------------------------------------------------
__global__ void k_place(const int* __restrict__ ei) {
    int e = blockIdx.x * blockDim.x + threadIdx.x;
    if (e >= N_EDGES) return;
    int src = __ldg(&ei[e]);
    int dst = __ldg(&ei[N_EDGES + e]);
    if (((unsigned)src >= N_NODES) | ((unsigned)dst >= N_NODES)) return;
    int pos = atomicAdd(&g_cnt[dst], 1);
    if (pos < CAP) g_srcs[dst * CAP + pos] = src;
}

// ---------------------------------------------------------------------------
// Kernel 3 (k_agg): h[n] = x[n] + sum of neighbor rows. One warp per node.
// Overflow belt: deg > CAP (P ~ 1e-30) -> full edge rescan.
// ---------------------------------------------------------------------------
__global__ void k_agg(const float* __restrict__ x, const int* __restrict__ ei) {
    int n    = (blockIdx.x * blockDim.x + threadIdx.x) >> 5;
    int lane = threadIdx.x & 31;
    if (n >= N_NODES) return;
    int cnt = g_cnt[n];
    float4 acc = __ldg((const float4*)(x + (size_t)n * D) + lane);

    if (cnt <= CAP) {
        const int* s = g_srcs + n * CAP;
        int j = 0;
        for (; j + 2 <= cnt; j += 2) {
            int s0 = __ldg(&s[j]);
            int s1 = __ldg(&s[j + 1]);
            float4 v0 = __ldg((const float4*)(x + (size_t)s0 * D) + lane);
            float4 v1 = __ldg((const float4*)(x + (size_t)s1 * D) + lane);
            acc.x += v0.x + v1.x; acc.y += v0.y + v1.y;
            acc.z += v0.z + v1.z; acc.w += v0.w + v1.w;
        }
        if (j < cnt) {
            int s0 = __ldg(&s[j]);
            float4 v0 = __ldg((const float4*)(x + (size_t)s0 * D) + lane);
            acc.x += v0.x; acc.y += v0.y; acc.z += v0.z; acc.w += v0.w;
        }
    } else {
        for (int e = 0; e < N_EDGES; e++) {
            if (__ldg(&ei[N_EDGES + e]) == n) {
                int s0 = __ldg(&ei[e]);
                if ((unsigned)s0 < N_NODES) {
                    float4 v0 = __ldg((const float4*)(x + (size_t)s0 * D) + lane);
                    acc.x += v0.x; acc.y += v0.y; acc.z += v0.z; acc.w += v0.w;
                }
            }
        }
    }
    *(float4*)(g_h + (size_t)n * D + lane * 4) = acc;
}

// ---------------------------------------------------------------------------
// Kernel 4: h1 = relu(h @ W1 + b1) + BN stat partials.  Packed-f32x2 GEMM.
// Tile: 128 rows x 128 cols, 256 threads, 8x8 per thread (4 row-pairs x 8 cols).
// acc[rp][c] is f32x2 over a row pair; B stored DUPLICATED in smem so each
// LDS.128 yields two (b,b) pairs; 32 fma.rn.f32x2 per k (vs 64 FFMA).
// Thread (tx=t&15, ty=t>>4): rows {ty*4..+3, 64+ty*4..+3},
//                            cols {g*32 + tx*2 + e : g<4, e<2}.
// ---------------------------------------------------------------------------
#define KC 16
__global__ void k_gemm1(const float* __restrict__ W1,
                        const float* __restrict__ b1) {
    __shared__ __align__(16) float As [KC][132];     // k-major A, pitch 132
    __shared__ __align__(16) float Bs2[KC][256];     // duplicated B
    __shared__ float s_sum[128];
    __shared__ float s_sq [128];

    int t  = threadIdx.x;
    int tx = t & 15;
    int ty = t >> 4;
    int rowBase = blockIdx.x * 128;

    if (t < 128) { s_sum[t] = 0.f; s_sq[t] = 0.f; }

    ull acc[4][8];
    #pragma unroll
    for (int i = 0; i < 4; i++)
        #pragma unroll
        for (int j = 0; j < 8; j++) acc[i][j] = 0ull;

    for (int kc = 0; kc < D; kc += KC) {
        // A tile: 128 rows x KC k.  512 float4 loads; transpose into As[k][m].
        #pragma unroll
        for (int i = 0; i < 2; i++) {
            int idx = t + i * 256;            // 0..511
            int m = idx >> 2, k4 = idx & 3;   // row m, k-quad k4
            int row = rowBase + m;
            float4 v = make_float4(0.f, 0.f, 0.f, 0.f);
            if (row < N_NODES)
                v = __ldg((const float4*)(g_h + (size_t)row * D + kc) + k4);
            As[k4 * 4 + 0][m] = v.x;
            As[k4 * 4 + 1][m] = v.y;
            As[k4 * 4 + 2][m] = v.z;
            As[k4 * 4 + 3][m] = v.w;
        }
        // B tile: KC k x 128 n, stored duplicated (n -> 2n, 2n+1).
        #pragma unroll
        for (int i = 0; i < 2; i++) {
            int idx = t + i * 256;            // 0..511
            int k = idx >> 5, n4 = idx & 31;
            float4 w = __ldg((const float4*)(W1 + (size_t)(kc + k) * D) + n4);
            float4* dst = (float4*)&Bs2[k][n4 * 8];
            dst[0] = make_float4(w.x, w.x, w.y, w.y);
            dst[1] = make_float4(w.z, w.z, w.w, w.w);
        }
        __syncthreads();

        #pragma unroll
        for (int k = 0; k < KC; k++) {
            ulonglong2 A0 = *(const ulonglong2*)&As[k][ty * 4];        // rp 0,1
            ulonglong2 A1 = *(const ulonglong2*)&As[k][64 + ty * 4];   // rp 2,3
            #pragma unroll
            for (int g = 0; g < 4; g++) {
                ulonglong2 B = *(const ulonglong2*)&Bs2[k][g * 64 + tx * 4];
                FMA2(acc[0][g * 2 + 0], A0.x, B.x);
                FMA2(acc[0][g * 2 + 1], A0.x, B.y);
                FMA2(acc[1][g * 2 + 0], A0.y, B.x);
                FMA2(acc[1][g * 2 + 1], A0.y, B.y);
                FMA2(acc[2][g * 2 + 0], A1.x, B.x);
                FMA2(acc[2][g * 2 + 1], A1.x, B.y);
                FMA2(acc[3][g * 2 + 0], A1.y, B.x);
                FMA2(acc[3][g * 2 + 1], A1.y, B.y);
            }
        }
        __syncthreads();
    }

    // Epilogue: bias + relu + store + per-column sum/sumsq partials.
    float bias[8], psum[8], psq[8];
    #pragma unroll
    for (int c = 0; c < 8; c++) {
        int col = (c >> 1) * 32 + tx * 2 + (c & 1);
        bias[c] = __ldg(&b1[col]);
        psum[c] = 0.f; psq[c] = 0.f;
    }

    #pragma unroll
    for (int rp = 0; rp < 4; rp++) {
        int rbase = (rp < 2) ? (ty * 4 + rp * 2) : (64 + ty * 4 + (rp - 2) * 2);
        int r0 = rowBase + rbase;
        int r1 = r0 + 1;
        bool ok0 = r0 < N_NODES, ok1 = r1 < N_NODES;
        #pragma unroll
        for (int g = 0; g < 4; g++) {
            float e0, o0, e1, o1;
            UNPK(e0, o0, acc[rp][g * 2 + 0]);   // (even row, odd row) @ col 2g
            UNPK(e1, o1, acc[rp][g * 2 + 1]);   // @ col 2g+1
            e0 = fmaxf(e0 + bias[g * 2 + 0], 0.f);
            e1 = fmaxf(e1 + bias[g * 2 + 1], 0.f);
            o0 = fmaxf(o0 + bias[g * 2 + 0], 0.f);
            o1 = fmaxf(o1 + bias[g * 2 + 1], 0.f);
            int coff = g * 32 + tx * 2;
            if (ok0) {
                *(float2*)(g_h1 + (size_t)r0 * D + coff) = make_float2(e0, e1);
                psum[g * 2 + 0] += e0; psq[g * 2 + 0] += e0 * e0;
                psum[g * 2 + 1] += e1; psq[g * 2 + 1] += e1 * e1;
            }
            if (ok1) {
                *(float2*)(g_h1 + (size_t)r1 * D + coff) = make_float2(o0, o1);
                psum[g * 2 + 0] += o0; psq[g * 2 + 0] += o0 * o0;
                psum[g * 2 + 1] += o1; psq[g * 2 + 1] += o1 * o1;
            }
        }
    }
    #pragma unroll
    for (int c = 0; c < 8; c++) {
        int col = (c >> 1) * 32 + tx * 2 + (c & 1);
        atomicAdd(&s_sum[col], psum[c]);
        atomicAdd(&s_sq [col], psq [c]);
    }
    __syncthreads();
    if (t < 128) {
        atomicAdd(&g_sum[t], s_sum[t]);
        atomicAdd(&g_sq [t], s_sq [t]);
    }
}

// ---------------------------------------------------------------------------
// Kernel 5 (1 block, 128 threads): finalize BN stats, fold into Weff/ceff.
// ---------------------------------------------------------------------------
__global__ void k_stats(const float* __restrict__ b2, const float* __restrict__ Wl,
                        const float* __restrict__ bl,
                        const float* __restrict__ gamma, const float* __restrict__ beta) {
    int f = threadIdx.x;   // 0..127
    float mean = g_sum[f] * (1.0f / N_NODES);
    float var  = g_sq [f] * (1.0f / N_NODES) - mean * mean;
    float g    = rsqrtf(var + BN_EPS) * gamma[f];

    float w2l0 = g_W2l[f * 2 + 0];
    float w2l1 = g_W2l[f * 2 + 1];
    g_Weff[f * 2 + 0] = g * w2l0;
    g_Weff[f * 2 + 1] = g * w2l1;

    float bias = beta[f] - mean * g;
    float p0 = bias * w2l0 + b2[f] * Wl[f * 2 + 0];
    float p1 = bias * w2l1 + b2[f] * Wl[f * 2 + 1];

    __shared__ float r0[128], r1[128];
    r0[f] = p0; r1[f] = p1;
    __syncthreads();
    for (int s = 64; s > 0; s >>= 1) {
        if (f < s) { r0[f] += r0[f + s]; r1[f] += r1[f + s]; }
        __syncthreads();
    }
    if (f == 0) {
        g_ceff[0] = r0[0] + bl[0];
        g_ceff[1] = r1[0] + bl[1];
    }
}

// ---------------------------------------------------------------------------
// Kernel 6: out[n,c] = dot(h1[n,:], Weff[:,c]) + ceff[c]. One warp per node.
// ---------------------------------------------------------------------------
__global__ void k_out(float* __restrict__ out) {
    __shared__ float w[256];
    __shared__ float c0s, c1s;
    int t = threadIdx.x;
    w[t] = g_Weff[t];
    if (t == 0) { c0s = g_ceff[0]; c1s = g_ceff[1]; }
    __syncthreads();

    int lane = t & 31;
    int n = (blockIdx.x * blockDim.x + t) >> 5;
    if (n >= N_NODES) return;

    float4 h = *(const float4*)(g_h1 + (size_t)n * D + lane * 4);
    int b = lane * 8;
    float s0 = h.x * w[b + 0] + h.y * w[b + 2] + h.z * w[b + 4] + h.w * w[b + 6];
    float s1 = h.x * w[b + 1] + h.y * w[b + 3] + h.z * w[b + 5] + h.w * w[b + 7];
    #pragma unroll
    for (int o = 16; o > 0; o >>= 1) {
        s0 += __shfl_down_sync(0xFFFFFFFFu, s0, o);
        s1 += __shfl_down_sync(0xFFFFFFFFu, s1, o);
    }
    if (lane == 0) {
        out[n * 2 + 0] = s0 + c0s;
        out[n * 2 + 1] = s1 + c1s;
    }
}

// ---------------------------------------------------------------------------
extern "C" void kernel_launch(void* const* d_in, const int* in_sizes, int n_in,
                              void* d_out, int out_size) {
    const float* x     = (const float*)d_in[0];
    const int*   ei    = (const int*)  d_in[1];   // int32 (JAX x64-disabled)
    const float* W1    = (const float*)d_in[2];
    const float* b1    = (const float*)d_in[3];
    const float* gamma = (const float*)d_in[4];
    const float* beta  = (const float*)d_in[5];
    const float* W2    = (const float*)d_in[6];
    const float* b2    = (const float*)d_in[7];
    const float* Wl    = (const float*)d_in[8];
    const float* bl    = (const float*)d_in[9];
    float*       out   = (float*)      d_out;

    // 1) zero counters/stats + W2l = W2@Wl (one merged launch)
    k_pre<<<NB_CNT + 17, 256>>>(W2, Wl);
    // 2) bucket edges by dst (one thread per edge)
    k_place<<<(N_EDGES + 255) / 256, 256>>>(ei);
    // 3) h = x + aggregate (one warp per node; sole writer of g_h)
    k_agg<<<(N_NODES * 32 + 255) / 256, 256>>>(x, ei);
    // 4) h1 = relu(h@W1+b1) + BN stat partials (f32x2 GEMM, 128-row tiles)
    k_gemm1<<<(N_NODES + 127) / 128, 256>>>(W1, b1);
    // 5) finalize BN + fold into Weff[128x2], ceff[2]
    k_stats<<<1, 128>>>(b2, Wl, bl, gamma, beta);
    // 6) out = h1 @ Weff + ceff
    k_out<<<(N_NODES * 32 + 255) / 256, 256>>>(out);
}

// round 10
// speedup vs baseline: 1.0926x; 1.0926x over previous
#include <cuda_runtime.h>

#define N_NODES 50000
#define N_EDGES 600000
#define D 128
#define CAP 64            // per-node neighbor bucket capacity (Poisson λ=12)
#define BN_EPS 1e-5f

typedef unsigned long long ull;

// Scratch (allocation-free rule: __device__ globals)
__device__ __align__(16) float g_h [N_NODES * D];   // x + aggregated neighbors
__device__ __align__(16) float g_h1[N_NODES * D];   // relu(h @ W1 + b1)
__device__ int   g_cnt [N_NODES];                   // in-degree counters
__device__ int   g_srcs[N_NODES * CAP];             // bucketed src lists
__device__ float g_sum[D];
__device__ float g_sq [D];
__device__ __align__(16) float g_W2l [D * 2];       // W2 @ Wl
__device__ __align__(16) float g_Weff[D * 2];
__device__ float g_ceff[2];

#define FMA2(d, a, b) \
    asm("fma.rn.f32x2 %0, %1, %2, %3;" : "=l"(d) : "l"(a), "l"(b), "l"(d))
#define UNPK(lo, hi, v) do { unsigned _u0, _u1; \
    asm("mov.b64 {%0, %1}, %2;" : "=r"(_u0), "=r"(_u1) : "l"(v)); \
    lo = __uint_as_float(_u0); hi = __uint_as_float(_u1); } while (0)

// ---------------------------------------------------------------------------
// Kernel 1 (k_pre): zero counters + stat accumulators + W2l = W2 @ Wl.
// ---------------------------------------------------------------------------
#define NB_CNT ((N_NODES + 255) / 256)
__global__ void k_pre(const float* __restrict__ W2, const float* __restrict__ Wl) {
    int b = blockIdx.x;
    if (b < NB_CNT) {
        int i = b * 256 + threadIdx.x;
        if (i < N_NODES) g_cnt[i] = 0;
        return;
    }
    if (b < NB_CNT + 16) {
        int f    = (b - NB_CNT) * 8 + (threadIdx.x >> 5);
        int lane = threadIdx.x & 31;
        float4 a  = __ldg((const float4*)(W2 + f * D) + lane);
        float4 w0 = __ldg((const float4*)Wl + lane * 2 + 0);
        float4 w1 = __ldg((const float4*)Wl + lane * 2 + 1);
        float s0 = a.x * w0.x + a.y * w0.z + a.z * w1.x + a.w * w1.z;
        float s1 = a.x * w0.y + a.y * w0.w + a.z * w1.y + a.w * w1.w;
        #pragma unroll
        for (int o = 16; o > 0; o >>= 1) {
            s0 += __shfl_down_sync(0xFFFFFFFFu, s0, o);
            s1 += __shfl_down_sync(0xFFFFFFFFu, s1, o);
        }
        if (lane == 0) {
            g_W2l[f * 2 + 0] = s0;
            g_W2l[f * 2 + 1] = s1;
        }
        return;
    }
    if (threadIdx.x < D) {
        g_sum[threadIdx.x] = 0.f;
        g_sq [threadIdx.x] = 0.f;
    }
}

// ---------------------------------------------------------------------------
// Kernel 2 (k_place): bucket edges by dst. One thread per edge (int32 index).
// ---------------------------------------------------------------------------
__global__ void k_place(const int* __restrict__ ei) {
    int e = blockIdx.x * blockDim.x + threadIdx.x;
    if (e >= N_EDGES) return;
    int src = __ldg(&ei[e]);
    int dst = __ldg(&ei[N_EDGES + e]);
    if (((unsigned)src >= N_NODES) | ((unsigned)dst >= N_NODES)) return;
    int pos = atomicAdd(&g_cnt[dst], 1);
    if (pos < CAP) g_srcs[dst * CAP + pos] = src;
}

// ---------------------------------------------------------------------------
// Kernel 3 (k_agg): h[n] = x[n] + sum of neighbor rows. One warp per node.
// Overflow belt: deg > CAP (P ~ 1e-30) -> full edge rescan.
// ---------------------------------------------------------------------------
__global__ void k_agg(const float* __restrict__ x, const int* __restrict__ ei) {
    int n    = (blockIdx.x * blockDim.x + threadIdx.x) >> 5;
    int lane = threadIdx.x & 31;
    if (n >= N_NODES) return;
    int cnt = g_cnt[n];
    float4 acc = __ldg((const float4*)(x + (size_t)n * D) + lane);

    if (cnt <= CAP) {
        const int* s = g_srcs + n * CAP;
        int j = 0;
        for (; j + 2 <= cnt; j += 2) {
            int s0 = __ldg(&s[j]);
            int s1 = __ldg(&s[j + 1]);
            float4 v0 = __ldg((const float4*)(x + (size_t)s0 * D) + lane);
            float4 v1 = __ldg((const float4*)(x + (size_t)s1 * D) + lane);
            acc.x += v0.x + v1.x; acc.y += v0.y + v1.y;
            acc.z += v0.z + v1.z; acc.w += v0.w + v1.w;
        }
        if (j < cnt) {
            int s0 = __ldg(&s[j]);
            float4 v0 = __ldg((const float4*)(x + (size_t)s0 * D) + lane);
            acc.x += v0.x; acc.y += v0.y; acc.z += v0.z; acc.w += v0.w;
        }
    } else {
        for (int e = 0; e < N_EDGES; e++) {
            if (__ldg(&ei[N_EDGES + e]) == n) {
                int s0 = __ldg(&ei[e]);
                if ((unsigned)s0 < N_NODES) {
                    float4 v0 = __ldg((const float4*)(x + (size_t)s0 * D) + lane);
                    acc.x += v0.x; acc.y += v0.y; acc.z += v0.z; acc.w += v0.w;
                }
            }
        }
    }
    *(float4*)(g_h + (size_t)n * D + lane * 4) = acc;
}

// ---------------------------------------------------------------------------
// Kernel 4: h1 = relu(h @ W1 + b1) + BN stat partials.  Packed-f32x2 GEMM.
// Tile: 128 rows x 128 cols, 256 threads, 8x8 per thread (4 row-pairs x 8 cols).
// __launch_bounds__(256, 2): cap regs at 128 so 2 blocks/SM (occ 25%) —
// R9 ran at 132 regs -> 1 block/SM -> latency-bound (issue 30.7%).
// ---------------------------------------------------------------------------
#define KC 16
__global__ void __launch_bounds__(256, 2)
k_gemm1(const float* __restrict__ W1, const float* __restrict__ b1) {
    __shared__ __align__(16) float As [KC][132];     // k-major A, pitch 132
    __shared__ __align__(16) float Bs2[KC][256];     // duplicated B
    __shared__ float s_sum[128];
    __shared__ float s_sq [128];

    int t  = threadIdx.x;
    int tx = t & 15;
    int ty = t >> 4;
    int rowBase = blockIdx.x * 128;

    if (t < 128) { s_sum[t] = 0.f; s_sq[t] = 0.f; }

    ull acc[4][8];
    #pragma unroll
    for (int i = 0; i < 4; i++)
        #pragma unroll
        for (int j = 0; j < 8; j++) acc[i][j] = 0ull;

    for (int kc = 0; kc < D; kc += KC) {
        // A tile: 128 rows x KC k.  512 float4 loads; transpose into As[k][m].
        #pragma unroll
        for (int i = 0; i < 2; i++) {
            int idx = t + i * 256;            // 0..511
            int m = idx >> 2, k4 = idx & 3;   // row m, k-quad k4
            int row = rowBase + m;
            float4 v = make_float4(0.f, 0.f, 0.f, 0.f);
            if (row < N_NODES)
                v = __ldg((const float4*)(g_h + (size_t)row * D + kc) + k4);
            As[k4 * 4 + 0][m] = v.x;
            As[k4 * 4 + 1][m] = v.y;
            As[k4 * 4 + 2][m] = v.z;
            As[k4 * 4 + 3][m] = v.w;
        }
        // B tile: KC k x 128 n, stored duplicated (n -> 2n, 2n+1).
        #pragma unroll
        for (int i = 0; i < 2; i++) {
            int idx = t + i * 256;            // 0..511
            int k = idx >> 5, n4 = idx & 31;
            float4 w = __ldg((const float4*)(W1 + (size_t)(kc + k) * D) + n4);
            float4* dst = (float4*)&Bs2[k][n4 * 8];
            dst[0] = make_float4(w.x, w.x, w.y, w.y);
            dst[1] = make_float4(w.z, w.z, w.w, w.w);
        }
        __syncthreads();

        #pragma unroll
        for (int k = 0; k < KC; k++) {
            ulonglong2 A0 = *(const ulonglong2*)&As[k][ty * 4];        // rp 0,1
            ulonglong2 A1 = *(const ulonglong2*)&As[k][64 + ty * 4];   // rp 2,3
            #pragma unroll
            for (int g = 0; g < 4; g++) {
                ulonglong2 B = *(const ulonglong2*)&Bs2[k][g * 64 + tx * 4];
                FMA2(acc[0][g * 2 + 0], A0.x, B.x);
                FMA2(acc[0][g * 2 + 1], A0.x, B.y);
                FMA2(acc[1][g * 2 + 0], A0.y, B.x);
                FMA2(acc[1][g * 2 + 1], A0.y, B.y);
                FMA2(acc[2][g * 2 + 0], A1.x, B.x);
                FMA2(acc[2][g * 2 + 1], A1.x, B.y);
                FMA2(acc[3][g * 2 + 0], A1.y, B.x);
                FMA2(acc[3][g * 2 + 1], A1.y, B.y);
            }
        }
        __syncthreads();
    }

    // Epilogue: bias + relu + store + per-column sum/sumsq partials.
    // Bias is loaded per column-group inside the loop (lower peak regs).
    float psum[8], psq[8];
    #pragma unroll
    for (int c = 0; c < 8; c++) { psum[c] = 0.f; psq[c] = 0.f; }

    #pragma unroll
    for (int rp = 0; rp < 4; rp++) {
        int rbase = (rp < 2) ? (ty * 4 + rp * 2) : (64 + ty * 4 + (rp - 2) * 2);
        int r0 = rowBase + rbase;
        int r1 = r0 + 1;
        bool ok0 = r0 < N_NODES, ok1 = r1 < N_NODES;
        #pragma unroll
        for (int g = 0; g < 4; g++) {
            int coff = g * 32 + tx * 2;
            float2 bb = *(const float2*)(b1 + coff);
            float e0, o0, e1, o1;
            UNPK(e0, o0, acc[rp][g * 2 + 0]);   // (even row, odd row) @ col coff
            UNPK(e1, o1, acc[rp][g * 2 + 1]);   // @ col coff+1
            e0 = fmaxf(e0 + bb.x, 0.f);
            e1 = fmaxf(e1 + bb.y, 0.f);
            o0 = fmaxf(o0 + bb.x, 0.f);
            o1 = fmaxf(o1 + bb.y, 0.f);
            if (ok0) {
                *(float2*)(g_h1 + (size_t)r0 * D + coff) = make_float2(e0, e1);
                psum[g * 2 + 0] += e0; psq[g * 2 + 0] += e0 * e0;
                psum[g * 2 + 1] += e1; psq[g * 2 + 1] += e1 * e1;
            }
            if (ok1) {
                *(float2*)(g_h1 + (size_t)r1 * D + coff) = make_float2(o0, o1);
                psum[g * 2 + 0] += o0; psq[g * 2 + 0] += o0 * o0;
                psum[g * 2 + 1] += o1; psq[g * 2 + 1] += o1 * o1;
            }
        }
    }
    #pragma unroll
    for (int c = 0; c < 8; c++) {
        int col = (c >> 1) * 32 + tx * 2 + (c & 1);
        atomicAdd(&s_sum[col], psum[c]);
        atomicAdd(&s_sq [col], psq [c]);
    }
    __syncthreads();
    if (t < 128) {
        atomicAdd(&g_sum[t], s_sum[t]);
        atomicAdd(&g_sq [t], s_sq [t]);
    }
}

// ---------------------------------------------------------------------------
// Kernel 5 (1 block, 128 threads): finalize BN stats, fold into Weff/ceff.
// ---------------------------------------------------------------------------
__global__ void k_stats(const float* __restrict__ b2, const float* __restrict__ Wl,
                        const float* __restrict__ bl,
                        const float* __restrict__ gamma, const float* __restrict__ beta) {
    int f = threadIdx.x;   // 0..127
    float mean = g_sum[f] * (1.0f / N_NODES);
    float var  = g_sq [f] * (1.0f / N_NODES) - mean * mean;
    float g    = rsqrtf(var + BN_EPS) * gamma[f];

    float w2l0 = g_W2l[f * 2 + 0];
    float w2l1 = g_W2l[f * 2 + 1];
    g_Weff[f * 2 + 0] = g * w2l0;
    g_Weff[f * 2 + 1] = g * w2l1;

    float bias = beta[f] - mean * g;
    float p0 = bias * w2l0 + b2[f] * Wl[f * 2 + 0];
    float p1 = bias * w2l1 + b2[f] * Wl[f * 2 + 1];

    __shared__ float r0[128], r1[128];
    r0[f] = p0; r1[f] = p1;
    __syncthreads();
    for (int s = 64; s > 0; s >>= 1) {
        if (f < s) { r0[f] += r0[f + s]; r1[f] += r1[f + s]; }
        __syncthreads();
    }
    if (f == 0) {
        g_ceff[0] = r0[0] + bl[0];
        g_ceff[1] = r1[0] + bl[1];
    }
}

// ---------------------------------------------------------------------------
// Kernel 6: out[n,c] = dot(h1[n,:], Weff[:,c]) + ceff[c]. One warp per node.
// ---------------------------------------------------------------------------
__global__ void k_out(float* __restrict__ out) {
    __shared__ float w[256];
    __shared__ float c0s, c1s;
    int t = threadIdx.x;
    w[t] = g_Weff[t];
    if (t == 0) { c0s = g_ceff[0]; c1s = g_ceff[1]; }
    __syncthreads();

    int lane = t & 31;
    int n = (blockIdx.x * blockDim.x + t) >> 5;
    if (n >= N_NODES) return;

    float4 h = *(const float4*)(g_h1 + (size_t)n * D + lane * 4);
    int b = lane * 8;
    float s0 = h.x * w[b + 0] + h.y * w[b + 2] + h.z * w[b + 4] + h.w * w[b + 6];
    float s1 = h.x * w[b + 1] + h.y * w[b + 3] + h.z * w[b + 5] + h.w * w[b + 7];
    #pragma unroll
    for (int o = 16; o > 0; o >>= 1) {
        s0 += __shfl_down_sync(0xFFFFFFFFu, s0, o);
        s1 += __shfl_down_sync(0xFFFFFFFFu, s1, o);
    }
    if (lane == 0) {
        out[n * 2 + 0] = s0 + c0s;
        out[n * 2 + 1] = s1 + c1s;
    }
}

// ---------------------------------------------------------------------------
extern "C" void kernel_launch(void* const* d_in, const int* in_sizes, int n_in,
                              void* d_out, int out_size) {
    const float* x     = (const float*)d_in[0];
    const int*   ei    = (const int*)  d_in[1];   // int32 (JAX x64-disabled)
    const float* W1    = (const float*)d_in[2];
    const float* b1    = (const float*)d_in[3];
    const float* gamma = (const float*)d_in[4];
    const float* beta  = (const float*)d_in[5];
    const float* W2    = (const float*)d_in[6];
    const float* b2    = (const float*)d_in[7];
    const float* Wl    = (const float*)d_in[8];
    const float* bl    = (const float*)d_in[9];
    float*       out   = (float*)      d_out;

    // 1) zero counters/stats + W2l = W2@Wl (one merged launch)
    k_pre<<<NB_CNT + 17, 256>>>(W2, Wl);
    // 2) bucket edges by dst (one thread per edge)
    k_place<<<(N_EDGES + 255) / 256, 256>>>(ei);
    // 3) h = x + aggregate (one warp per node; sole writer of g_h)
    k_agg<<<(N_NODES * 32 + 255) / 256, 256>>>(x, ei);
    // 4) h1 = relu(h@W1+b1) + BN stat partials (f32x2 GEMM, occ-fixed)
    k_gemm1<<<(N_NODES + 127) / 128, 256>>>(W1, b1);
    // 5) finalize BN + fold into Weff[128x2], ceff[2]
    k_stats<<<1, 128>>>(b2, Wl, bl, gamma, beta);
    // 6) out = h1 @ Weff + ceff
    k_out<<<(N_NODES * 32 + 255) / 256, 256>>>(out);
}